// round 1
// baseline (speedup 1.0000x reference)
#include <cuda_runtime.h>

#define B_  32
#define C_  128
#define L_  256
#define CC_ (C_ * C_)      // 16384
#define BCC_ (B_ * CC_)    // 524288

// Scratch (device globals — no allocations allowed)
__device__ float g_diff[BCC_];      // [b][i][j] pairwise L1
__device__ float g_rnorm[CC_];      // 1 / max(||diff[:,i,j]||_2, 1e-12)
__device__ float g_tmpS[BCC_];      // exp(relu((1-diffn)*a))
__device__ float g_rcs[B_ * C_];    // 1 / column sums of tmpS
__device__ float g_y[B_ * C_ * L_]; // adj^T x

// ---------------------------------------------------------------------------
// Kernel A: diff[b,i,j] = sum_l |x[b,i,l] - x[b,j,l]|
// grid (8 i-tiles, 32 b), 128 threads (one per j). Per l-chunk of 32, stage
// all 128 rows of x[b] in smem (pad 36 -> conflict-free float4 LDS).
// ---------------------------------------------------------------------------
__global__ void k_diff(const float* __restrict__ x) {
    __shared__ float sx[C_][36];
    const int b  = blockIdx.y;
    const int i0 = blockIdx.x * 16;
    const int j  = threadIdx.x;
    const float* xb = x + b * C_ * L_;

    float acc[16];
#pragma unroll
    for (int t = 0; t < 16; t++) acc[t] = 0.f;

#pragma unroll 1
    for (int lc = 0; lc < L_; lc += 32) {
        __syncthreads();
#pragma unroll
        for (int rep = 0; rep < 32; rep++) {
            int idx = rep * 128 + threadIdx.x;
            int r = idx >> 5, c = idx & 31;
            sx[r][c] = xb[r * L_ + lc + c];
        }
        __syncthreads();
#pragma unroll
        for (int l4 = 0; l4 < 8; l4++) {
            float4 xj = *reinterpret_cast<const float4*>(&sx[j][l4 * 4]);
#pragma unroll
            for (int ii = 0; ii < 16; ii++) {
                float4 xi = *reinterpret_cast<const float4*>(&sx[i0 + ii][l4 * 4]);
                acc[ii] += fabsf(xi.x - xj.x) + fabsf(xi.y - xj.y)
                         + fabsf(xi.z - xj.z) + fabsf(xi.w - xj.w);
            }
        }
    }
#pragma unroll
    for (int ii = 0; ii < 16; ii++)
        g_diff[b * CC_ + (i0 + ii) * C_ + j] = acc[ii];
}

// ---------------------------------------------------------------------------
// Kernel B1: rnorm[i,j] = 1 / max(sqrt(sum_b diff^2), 1e-12)
// ---------------------------------------------------------------------------
__global__ void k_rnorm() {
    int idx = blockIdx.x * 256 + threadIdx.x; // 64 blocks * 256 = 16384
    float ss = 0.f;
#pragma unroll
    for (int b = 0; b < B_; b++) {
        float v = g_diff[b * CC_ + idx];
        ss += v * v;
    }
    g_rnorm[idx] = 1.f / fmaxf(sqrtf(ss), 1e-12f);
}

// ---------------------------------------------------------------------------
// Kernel B2: tmpS = exp(relu((1 - diff*rnorm) * a)); rcs[b,j] = 1/sum_i tmpS
// grid 32 (b), 128 threads (j). All loads coalesced across j.
// ---------------------------------------------------------------------------
__global__ void k_tmps(const float* __restrict__ a) {
    const int b = blockIdx.x;
    const int j = threadIdx.x;
    float cs = 0.f;
#pragma unroll 4
    for (int i = 0; i < C_; i++) {
        int ij = i * C_ + j;
        float d = g_diff[b * CC_ + ij] * g_rnorm[ij];
        float v = __expf(fmaxf((1.f - d) * a[ij], 0.f));
        g_tmpS[b * CC_ + ij] = v;
        cs += v;
    }
    g_rcs[b * C_ + j] = 1.f / cs;
}

// ---------------------------------------------------------------------------
// Kernel C: y[b,j,l] = rcs[b,j] * sum_i tmpS[b,i,j] * x[b,i,l]
// Batched GEMM (contraction index i is the SLOW axis of both operands — loads
// land coalesced directly into [i][j] / [i][l] smem tiles).
// grid (4 l-tiles, 2 j-tiles, 32 b), 256 threads, 4x4 register tile.
// ---------------------------------------------------------------------------
__global__ void k_y(const float* __restrict__ x) {
    __shared__ float sS[16][64];
    __shared__ float sX[16][64];
    const int b  = blockIdx.z;
    const int j0 = blockIdx.y * 64;
    const int l0 = blockIdx.x * 64;
    const int tid = threadIdx.x;
    const int tx = tid & 15, ty = tid >> 4;

    float acc[4][4];
#pragma unroll
    for (int r = 0; r < 4; r++)
#pragma unroll
        for (int c = 0; c < 4; c++) acc[r][c] = 0.f;

    const float* Sb = g_tmpS + b * CC_;
    const float* Xb = x + b * C_ * L_;

#pragma unroll 1
    for (int i0 = 0; i0 < C_; i0 += 16) {
        __syncthreads();
#pragma unroll
        for (int rep = 0; rep < 4; rep++) {
            int idx = rep * 256 + tid;
            int r = idx >> 6, c = idx & 63;
            sS[r][c] = Sb[(i0 + r) * C_ + j0 + c];
            sX[r][c] = Xb[(i0 + r) * L_ + l0 + c];
        }
        __syncthreads();
#pragma unroll
        for (int i = 0; i < 16; i++) {
            float4 av = *reinterpret_cast<const float4*>(&sS[i][ty * 4]);
            float4 bv = *reinterpret_cast<const float4*>(&sX[i][tx * 4]);
            float a4[4] = {av.x, av.y, av.z, av.w};
            float b4[4] = {bv.x, bv.y, bv.z, bv.w};
#pragma unroll
            for (int r = 0; r < 4; r++)
#pragma unroll
                for (int c = 0; c < 4; c++)
                    acc[r][c] += a4[r] * b4[c];
        }
    }
#pragma unroll
    for (int r = 0; r < 4; r++) {
        int jj = j0 + ty * 4 + r;
        float rc = g_rcs[b * C_ + jj];
        float4 v = make_float4(acc[r][0] * rc, acc[r][1] * rc,
                               acc[r][2] * rc, acc[r][3] * rc);
        *reinterpret_cast<float4*>(&g_y[b * C_ * L_ + jj * L_ + l0 + tx * 4]) = v;
    }
}

// ---------------------------------------------------------------------------
// Kernel D: out[r,m] = relu( sum_l X[r,l]*T0[l,m] - sum_l Y[r,l]*T1[l,m] )
// with rows r = b*128+j flattened to 4096. Single GEMM with K=512 (two passes),
// sign folded into the T1 smem load. A-tile is transposed on store into smem
// ([k][row], pad 68 -> 16B-aligned float4 rows, mild 2-way store conflicts).
// grid (4 m-tiles, 64 r-tiles), 256 threads, 4x4 register tile.
// ---------------------------------------------------------------------------
__global__ void k_out(const float* __restrict__ x,
                      const float* __restrict__ Theta,
                      float* __restrict__ out) {
    __shared__ float sA[16][68];
    __shared__ float sB[16][64];
    const int r0 = blockIdx.y * 64;
    const int m0 = blockIdx.x * 64;
    const int tid = threadIdx.x;
    const int tx = tid & 15, ty = tid >> 4;

    float acc[4][4];
#pragma unroll
    for (int r = 0; r < 4; r++)
#pragma unroll
        for (int c = 0; c < 4; c++) acc[r][c] = 0.f;

#pragma unroll 1
    for (int pass = 0; pass < 2; pass++) {
        const float* A  = pass ? g_y : x;            // both [4096][256] row-major
        const float* Bm = pass ? (Theta + L_ * L_) : Theta;
        const float sign = pass ? -1.f : 1.f;
#pragma unroll 1
        for (int k0 = 0; k0 < L_; k0 += 16) {
            __syncthreads();
#pragma unroll
            for (int rep = 0; rep < 4; rep++) {
                int idx = rep * 256 + tid;
                int row = idx >> 4, kk = idx & 15;        // A: 64 rows x 16 k
                sA[kk][row] = A[(r0 + row) * L_ + k0 + kk];
                int rr = idx >> 6, cc = idx & 63;         // B: 16 k x 64 m
                sB[rr][cc] = sign * Bm[(k0 + rr) * L_ + m0 + cc];
            }
            __syncthreads();
#pragma unroll
            for (int i = 0; i < 16; i++) {
                float4 av = *reinterpret_cast<const float4*>(&sA[i][ty * 4]);
                float4 bv = *reinterpret_cast<const float4*>(&sB[i][tx * 4]);
                float a4[4] = {av.x, av.y, av.z, av.w};
                float b4[4] = {bv.x, bv.y, bv.z, bv.w};
#pragma unroll
                for (int r = 0; r < 4; r++)
#pragma unroll
                    for (int c = 0; c < 4; c++)
                        acc[r][c] += a4[r] * b4[c];
            }
        }
    }
#pragma unroll
    for (int r = 0; r < 4; r++) {
        int row = r0 + ty * 4 + r;
        float4 v = make_float4(fmaxf(acc[r][0], 0.f), fmaxf(acc[r][1], 0.f),
                               fmaxf(acc[r][2], 0.f), fmaxf(acc[r][3], 0.f));
        *reinterpret_cast<float4*>(&out[row * L_ + m0 + tx * 4]) = v;
    }
}

// ---------------------------------------------------------------------------
extern "C" void kernel_launch(void* const* d_in, const int* in_sizes, int n_in,
                              void* d_out, int out_size) {
    const float* x     = (const float*)d_in[0];   // [32,128,256]
    const float* a     = (const float*)d_in[1];   // [128,128]
    const float* Theta = (const float*)d_in[2];   // [2,256,256]
    float* out = (float*)d_out;                   // [32,128,256]

    k_diff <<<dim3(8, 32),      128>>>(x);
    k_rnorm<<<64,               256>>>();
    k_tmps <<<32,               128>>>(a);
    k_y    <<<dim3(4, 2, 32),   256>>>(x);
    k_out  <<<dim3(4, 64),      256>>>(x, Theta, out);
}

// round 3
// speedup vs baseline: 1.0624x; 1.0624x over previous
#include <cuda_runtime.h>
#include <cstdint>

#define B_  32
#define C_  128
#define L_  256
#define CC_ (C_ * C_)      // 16384
#define BCC_ (B_ * CC_)    // 524288

// Scratch (device globals — no allocations allowed)
__device__ float g_diff[BCC_];        // [b][i][j] pairwise L1
__device__ float g_rnorm[CC_];        // 1 / max(||diff[:,i,j]||_2, 1e-12)
__device__ float g_tmpS[BCC_];        // exp(relu((1-diffn)*a))
__device__ float g_rcs[B_ * C_];      // 1 / column sums of tmpS
__device__ float g_y[B_ * C_ * L_];   // adj^T x  (rcs folded in)
__device__ float g_tt[256 * 512];     // B operand: [n][k] K-major, sign-folded
                                      //   k<256: Theta0[k][n],  k>=256: -Theta1[k-256][n]

// ===========================================================================
// helpers
// ===========================================================================
__device__ __forceinline__ float tf32_hi(float v) {
    // keep exactly the 10 tf32 mantissa bits
    return __uint_as_float(__float_as_uint(v) & 0xFFFFE000u);
}
__device__ __forceinline__ float cvt_tf32(float v) {
    uint32_t r;
    asm("cvt.rna.tf32.f32 %0, %1;" : "=r"(r) : "f"(v));
    return __uint_as_float(r);
}
__device__ __forceinline__ void mma_16n8k8(float c[4], const uint32_t a[4],
                                           const uint32_t b[2]) {
    asm volatile(
        "mma.sync.aligned.m16n8k8.row.col.f32.tf32.tf32.f32 "
        "{%0,%1,%2,%3}, {%4,%5,%6,%7}, {%8,%9}, {%0,%1,%2,%3};"
        : "+f"(c[0]), "+f"(c[1]), "+f"(c[2]), "+f"(c[3])
        : "r"(a[0]), "r"(a[1]), "r"(a[2]), "r"(a[3]), "r"(b[0]), "r"(b[1]));
}

// ---------------------------------------------------------------------------
// Kernel A: diff[b,i,j] = sum_l |x[b,i,l] - x[b,j,l]|
// grid (8 i-tiles, 32 b), 256 threads: thread = (half, j); each half does 8 i.
// ---------------------------------------------------------------------------
__global__ void k_diff(const float* __restrict__ x) {
    __shared__ float sx[C_][36];
    const int b    = blockIdx.y;
    const int tid  = threadIdx.x;
    const int j    = tid & 127;
    const int half = tid >> 7;
    const int i0   = blockIdx.x * 16 + half * 8;
    const float* xb = x + b * C_ * L_;

    float acc[8];
#pragma unroll
    for (int t = 0; t < 8; t++) acc[t] = 0.f;

#pragma unroll 1
    for (int lc = 0; lc < L_; lc += 32) {
        __syncthreads();
#pragma unroll
        for (int rep = 0; rep < 16; rep++) {
            int idx = rep * 256 + tid;
            int r = idx >> 5, c = idx & 31;
            sx[r][c] = xb[r * L_ + lc + c];
        }
        __syncthreads();
#pragma unroll
        for (int l4 = 0; l4 < 8; l4++) {
            float4 xj = *reinterpret_cast<const float4*>(&sx[j][l4 * 4]);
#pragma unroll
            for (int ii = 0; ii < 8; ii++) {
                float4 xi = *reinterpret_cast<const float4*>(&sx[i0 + ii][l4 * 4]);
                acc[ii] += fabsf(xi.x - xj.x) + fabsf(xi.y - xj.y)
                         + fabsf(xi.z - xj.z) + fabsf(xi.w - xj.w);
            }
        }
    }
#pragma unroll
    for (int ii = 0; ii < 8; ii++)
        g_diff[b * CC_ + (i0 + ii) * C_ + j] = acc[ii];
}

// ---------------------------------------------------------------------------
// Kernel B1: rnorm[i,j] = 1 / max(sqrt(sum_b diff^2), 1e-12)
// ---------------------------------------------------------------------------
__global__ void k_rnorm() {
    int idx = blockIdx.x * 256 + threadIdx.x;
    float ss = 0.f;
#pragma unroll
    for (int b = 0; b < B_; b++) {
        float v = g_diff[b * CC_ + idx];
        ss += v * v;
    }
    g_rnorm[idx] = 1.f / fmaxf(sqrtf(ss), 1e-12f);
}

// ---------------------------------------------------------------------------
// Kernel B2: tmpS = exp(relu((1 - diff*rnorm) * a)); rcs[b,j] = 1/sum_i tmpS
// ---------------------------------------------------------------------------
__global__ void k_tmps(const float* __restrict__ a) {
    const int b = blockIdx.x;
    const int j = threadIdx.x;
    float cs = 0.f;
#pragma unroll 4
    for (int i = 0; i < C_; i++) {
        int ij = i * C_ + j;
        float d = g_diff[b * CC_ + ij] * g_rnorm[ij];
        float v = __expf(fmaxf((1.f - d) * a[ij], 0.f));
        g_tmpS[b * CC_ + ij] = v;
        cs += v;
    }
    g_rcs[b * C_ + j] = 1.f / cs;
}

// ---------------------------------------------------------------------------
// Kernel Tt: g_tt[n][k] = Theta0[k][n] (k<256) | -Theta1[k-256][n] (k>=256)
// ---------------------------------------------------------------------------
__global__ void k_tt(const float* __restrict__ Theta) {
    __shared__ float t[32][33];
    const int kt = blockIdx.x * 32, nt = blockIdx.y * 32;
    const int tx = threadIdx.x & 31, ty = threadIdx.x >> 5;  // ty 0..7
#pragma unroll
    for (int r = 0; r < 32; r += 8) {
        int k = kt + ty + r;
        int n = nt + tx;
        float v = (k < 256) ? Theta[k * 256 + n] : -Theta[65536 + (k - 256) * 256 + n];
        t[ty + r][tx] = v;
    }
    __syncthreads();
#pragma unroll
    for (int r = 0; r < 32; r += 8) {
        int n = nt + ty + r;
        int k = kt + tx;
        g_tt[n * 512 + k] = t[tx][ty + r];
    }
}

// ---------------------------------------------------------------------------
// Kernel C: y[b,j,l] = rcs[b,j] * sum_i tmpS[b,i,j] * x[b,i,l]
// grid (4 l, 4 j, 32 b) = 512 CTAs, 128 threads, 32j x 64l tile, 4x4/thread.
// ---------------------------------------------------------------------------
__global__ void k_y(const float* __restrict__ x) {
    __shared__ float sS[16][32];
    __shared__ float sX[16][64];
    const int b  = blockIdx.z;
    const int j0 = blockIdx.y * 32;
    const int l0 = blockIdx.x * 64;
    const int tid = threadIdx.x;
    const int tx = tid & 15, ty = tid >> 4;  // ty 0..7

    float acc[4][4];
#pragma unroll
    for (int r = 0; r < 4; r++)
#pragma unroll
        for (int c = 0; c < 4; c++) acc[r][c] = 0.f;

    const float* Sb = g_tmpS + b * CC_;
    const float* Xb = x + b * C_ * L_;

#pragma unroll 1
    for (int i0 = 0; i0 < C_; i0 += 16) {
        __syncthreads();
#pragma unroll
        for (int rep = 0; rep < 4; rep++) {
            int idx = rep * 128 + tid;
            int r = idx >> 5, c = idx & 31;
            sS[r][c] = Sb[(i0 + r) * C_ + j0 + c];
        }
#pragma unroll
        for (int rep = 0; rep < 8; rep++) {
            int idx = rep * 128 + tid;
            int r = idx >> 6, c = idx & 63;
            sX[r][c] = Xb[(i0 + r) * L_ + l0 + c];
        }
        __syncthreads();
#pragma unroll
        for (int i = 0; i < 16; i++) {
            float4 av = *reinterpret_cast<const float4*>(&sS[i][ty * 4]);
            float4 bv = *reinterpret_cast<const float4*>(&sX[i][tx * 4]);
            float a4[4] = {av.x, av.y, av.z, av.w};
            float b4[4] = {bv.x, bv.y, bv.z, bv.w};
#pragma unroll
            for (int r = 0; r < 4; r++)
#pragma unroll
                for (int c = 0; c < 4; c++)
                    acc[r][c] += a4[r] * b4[c];
        }
    }
#pragma unroll
    for (int r = 0; r < 4; r++) {
        int jj = j0 + ty * 4 + r;
        float rc = g_rcs[b * C_ + jj];
        float4 v = make_float4(acc[r][0] * rc, acc[r][1] * rc,
                               acc[r][2] * rc, acc[r][3] * rc);
        *reinterpret_cast<float4*>(&g_y[b * C_ * L_ + jj * L_ + l0 + tx * 4]) = v;
    }
}

// ---------------------------------------------------------------------------
// Kernel D (tensor core, mma.sync tf32, 3-pass hi/lo split):
//   out = relu( [x | g_y] @ g_tt^T ),  M=4096, N=256, K=512
// CTA: 64x64 tile, 128 threads (4 warps in 2x2, 32x32 warp tiles).
// grid (4 n, 64 m) = 256 CTAs. K-chunks of 32, smem padded to 36 floats/row
// (fragment LDS is conflict-free: bank == lane).
// ---------------------------------------------------------------------------
__global__ void __launch_bounds__(128) k_out_mma(const float* __restrict__ x,
                                                 float* __restrict__ out) {
    __shared__ float sAH[64][36], sAL[64][36];
    __shared__ float sBH[64][36], sBL[64][36];

    const int tid  = threadIdx.x;
    const int lane = tid & 31, wid = tid >> 5;
    const int n0 = blockIdx.x * 64;
    const int r0 = blockIdx.y * 64;
    const int wm = (wid >> 1) * 32;   // warp m offset in tile
    const int wn = (wid & 1) * 32;    // warp n offset in tile
    const int qr = lane >> 2;         // 0..7
    const int qc = lane & 3;          // 0..3

    float acc[2][4][4];
#pragma unroll
    for (int mi = 0; mi < 2; mi++)
#pragma unroll
        for (int ni = 0; ni < 4; ni++)
#pragma unroll
            for (int e = 0; e < 4; e++) acc[mi][ni][e] = 0.f;

#pragma unroll 1
    for (int s = 0; s < 16; s++) {
        const float* Asrc = (s < 8) ? (x   + (size_t)r0 * L_ + s * 32)
                                    : (g_y + (size_t)r0 * L_ + (s - 8) * 32);
        const float* Bsrc = g_tt + (size_t)n0 * 512 + s * 32;

        __syncthreads();
#pragma unroll
        for (int it = 0; it < 4; it++) {
            int idx = it * 128 + tid;
            int row = idx >> 3, c4 = (idx & 7) * 4;
            float4 v = *reinterpret_cast<const float4*>(Asrc + row * L_ + c4);
            float4 h = make_float4(tf32_hi(v.x), tf32_hi(v.y), tf32_hi(v.z), tf32_hi(v.w));
            float4 l = make_float4(cvt_tf32(v.x - h.x), cvt_tf32(v.y - h.y),
                                   cvt_tf32(v.z - h.z), cvt_tf32(v.w - h.w));
            *reinterpret_cast<float4*>(&sAH[row][c4]) = h;
            *reinterpret_cast<float4*>(&sAL[row][c4]) = l;

            float4 w = *reinterpret_cast<const float4*>(Bsrc + row * 512 + c4);
            float4 hb = make_float4(tf32_hi(w.x), tf32_hi(w.y), tf32_hi(w.z), tf32_hi(w.w));
            float4 lb = make_float4(cvt_tf32(w.x - hb.x), cvt_tf32(w.y - hb.y),
                                    cvt_tf32(w.z - hb.z), cvt_tf32(w.w - hb.w));
            *reinterpret_cast<float4*>(&sBH[row][c4]) = hb;
            *reinterpret_cast<float4*>(&sBL[row][c4]) = lb;
        }
        __syncthreads();

#pragma unroll
        for (int k8 = 0; k8 < 4; k8++) {
            const int k = k8 * 8;
            uint32_t ah[2][4], al[2][4], bh[4][2], bl[4][2];
#pragma unroll
            for (int mi = 0; mi < 2; mi++) {
                int r = wm + mi * 16 + qr;
                ah[mi][0] = __float_as_uint(sAH[r    ][k + qc    ]);
                ah[mi][1] = __float_as_uint(sAH[r + 8][k + qc    ]);
                ah[mi][2] = __float_as_uint(sAH[r    ][k + qc + 4]);
                ah[mi][3] = __float_as_uint(sAH[r + 8][k + qc + 4]);
                al[mi][0] = __float_as_uint(sAL[r    ][k + qc    ]);
                al[mi][1] = __float_as_uint(sAL[r + 8][k + qc    ]);
                al[mi][2] = __float_as_uint(sAL[r    ][k + qc + 4]);
                al[mi][3] = __float_as_uint(sAL[r + 8][k + qc + 4]);
            }
#pragma unroll
            for (int ni = 0; ni < 4; ni++) {
                int n = wn + ni * 8 + qr;
                bh[ni][0] = __float_as_uint(sBH[n][k + qc    ]);
                bh[ni][1] = __float_as_uint(sBH[n][k + qc + 4]);
                bl[ni][0] = __float_as_uint(sBL[n][k + qc    ]);
                bl[ni][1] = __float_as_uint(sBL[n][k + qc + 4]);
            }
            // pass 1: AH*BH (8 independent accumulator chains)
#pragma unroll
            for (int mi = 0; mi < 2; mi++)
#pragma unroll
                for (int ni = 0; ni < 4; ni++)
                    mma_16n8k8(acc[mi][ni], ah[mi], bh[ni]);
            // pass 2: AL*BH
#pragma unroll
            for (int mi = 0; mi < 2; mi++)
#pragma unroll
                for (int ni = 0; ni < 4; ni++)
                    mma_16n8k8(acc[mi][ni], al[mi], bh[ni]);
            // pass 3: AH*BL
#pragma unroll
            for (int mi = 0; mi < 2; mi++)
#pragma unroll
                for (int ni = 0; ni < 4; ni++)
                    mma_16n8k8(acc[mi][ni], ah[mi], bl[ni]);
        }
    }

    // ---- epilogue: relu + store (float2 per fragment half) ----
#pragma unroll
    for (int mi = 0; mi < 2; mi++) {
        int row = r0 + wm + mi * 16 + qr;
#pragma unroll
        for (int ni = 0; ni < 4; ni++) {
            int col = n0 + wn + ni * 8 + qc * 2;
            float2 v0 = make_float2(fmaxf(acc[mi][ni][0], 0.f),
                                    fmaxf(acc[mi][ni][1], 0.f));
            float2 v1 = make_float2(fmaxf(acc[mi][ni][2], 0.f),
                                    fmaxf(acc[mi][ni][3], 0.f));
            *reinterpret_cast<float2*>(out + (size_t)row * L_ + col) = v0;
            *reinterpret_cast<float2*>(out + (size_t)(row + 8) * L_ + col) = v1;
        }
    }
}

// ---------------------------------------------------------------------------
extern "C" void kernel_launch(void* const* d_in, const int* in_sizes, int n_in,
                              void* d_out, int out_size) {
    const float* x     = (const float*)d_in[0];   // [32,128,256]
    const float* a     = (const float*)d_in[1];   // [128,128]
    const float* Theta = (const float*)d_in[2];   // [2,256,256]
    float* out = (float*)d_out;                   // [32,128,256]

    k_tt    <<<dim3(16, 8),    256>>>(Theta);
    k_diff  <<<dim3(8, 32),    256>>>(x);
    k_rnorm <<<64,             256>>>();
    k_tmps  <<<32,             128>>>(a);
    k_y     <<<dim3(4, 4, 32), 128>>>(x);
    k_out_mma<<<dim3(4, 64),   128>>>(x, out);
}

// round 4
// speedup vs baseline: 1.4945x; 1.4068x over previous
#include <cuda_runtime.h>
#include <cstdint>

#define B_  32
#define C_  128
#define L_  256
#define CC_ (C_ * C_)      // 16384
#define BCC_ (B_ * CC_)    // 524288

// Scratch (device globals — no allocations allowed)
__device__ float g_diff[BCC_];        // [b][i][j] pairwise L1
__device__ float g_rnorm[CC_];        // 1 / max(||diff[:,i,j]||_2, 1e-12)
__device__ float g_tmpS[BCC_];        // exp(relu((1-diffn)*a))
__device__ float g_rcs[B_ * C_];      // 1 / column sums of tmpS
__device__ float g_y[B_ * C_ * L_];   // adj^T x  (rcs folded in)
__device__ float g_tt[256 * 512];     // B operand: [n][k] K-major, sign-folded
                                      //   k<256: Theta0[k][n],  k>=256: -Theta1[k-256][n]

// ===========================================================================
// helpers
// ===========================================================================
__device__ __forceinline__ float tf32_hi(float v) {
    return __uint_as_float(__float_as_uint(v) & 0xFFFFE000u);
}
__device__ __forceinline__ float cvt_tf32(float v) {
    uint32_t r;
    asm("cvt.rna.tf32.f32 %0, %1;" : "=r"(r) : "f"(v));
    return __uint_as_float(r);
}
__device__ __forceinline__ void mma_16n8k8(float c[4], const uint32_t a[4],
                                           const uint32_t b[2]) {
    asm volatile(
        "mma.sync.aligned.m16n8k8.row.col.f32.tf32.tf32.f32 "
        "{%0,%1,%2,%3}, {%4,%5,%6,%7}, {%8,%9}, {%0,%1,%2,%3};"
        : "+f"(c[0]), "+f"(c[1]), "+f"(c[2]), "+f"(c[3])
        : "r"(a[0]), "r"(a[1]), "r"(a[2]), "r"(a[3]), "r"(b[0]), "r"(b[1]));
}

// ---------------------------------------------------------------------------
// Kernel A: diff[b,i,j] = sum_l |x[b,i,l] - x[b,j,l]|
// grid (8 i-tiles, 32 b), 256 threads: thread = (half, j); each half does 8 i.
// ---------------------------------------------------------------------------
__global__ void k_diff(const float* __restrict__ x) {
    __shared__ float sx[C_][36];
    const int b    = blockIdx.y;
    const int tid  = threadIdx.x;
    const int j    = tid & 127;
    const int half = tid >> 7;
    const int i0   = blockIdx.x * 16 + half * 8;
    const float* xb = x + b * C_ * L_;

    float acc[8];
#pragma unroll
    for (int t = 0; t < 8; t++) acc[t] = 0.f;

#pragma unroll 1
    for (int lc = 0; lc < L_; lc += 32) {
        __syncthreads();
#pragma unroll
        for (int rep = 0; rep < 16; rep++) {
            int idx = rep * 256 + tid;
            int r = idx >> 5, c = idx & 31;
            sx[r][c] = xb[r * L_ + lc + c];
        }
        __syncthreads();
#pragma unroll
        for (int l4 = 0; l4 < 8; l4++) {
            float4 xj = *reinterpret_cast<const float4*>(&sx[j][l4 * 4]);
#pragma unroll
            for (int ii = 0; ii < 8; ii++) {
                float4 xi = *reinterpret_cast<const float4*>(&sx[i0 + ii][l4 * 4]);
                acc[ii] += fabsf(xi.x - xj.x) + fabsf(xi.y - xj.y)
                         + fabsf(xi.z - xj.z) + fabsf(xi.w - xj.w);
            }
        }
    }
#pragma unroll
    for (int ii = 0; ii < 8; ii++)
        g_diff[b * CC_ + (i0 + ii) * C_ + j] = acc[ii];
}

// ---------------------------------------------------------------------------
// Kernel B1: rnorm[i,j] = 1 / max(sqrt(sum_b diff^2), 1e-12)
// ---------------------------------------------------------------------------
__global__ void k_rnorm() {
    int idx = blockIdx.x * 256 + threadIdx.x;
    float ss = 0.f;
#pragma unroll
    for (int b = 0; b < B_; b++) {
        float v = g_diff[b * CC_ + idx];
        ss += v * v;
    }
    g_rnorm[idx] = 1.f / fmaxf(sqrtf(ss), 1e-12f);
}

// ---------------------------------------------------------------------------
// Kernel B2: tmpS = exp(relu((1 - diff*rnorm) * a)); rcs[b,j] = 1/sum_i tmpS
// Re-parallelized: grid (32 b, 4 j-tiles) = 128 CTAs x 256 threads.
// thread = (ty = i-group 0..7, tx = j-lane 0..31); 16 independent i's per
// thread (MLP ~16), smem reduction over ty for the column sum.
// ---------------------------------------------------------------------------
__global__ void k_tmps(const float* __restrict__ a) {
    __shared__ float red[8][32];
    const int b  = blockIdx.x;
    const int j0 = blockIdx.y * 32;
    const int tx = threadIdx.x & 31;
    const int ty = threadIdx.x >> 5;   // 0..7
    const int j  = j0 + tx;

    float cs = 0.f;
#pragma unroll
    for (int ii = 0; ii < 16; ii++) {
        int i  = ii * 8 + ty;
        int ij = i * C_ + j;
        float d = g_diff[b * CC_ + ij] * g_rnorm[ij];
        float v = __expf(fmaxf((1.f - d) * a[ij], 0.f));
        g_tmpS[b * CC_ + ij] = v;
        cs += v;
    }
    red[ty][tx] = cs;
    __syncthreads();
    if (ty == 0) {
        float s = red[0][tx];
#pragma unroll
        for (int r = 1; r < 8; r++) s += red[r][tx];
        g_rcs[b * C_ + j] = 1.f / s;
    }
}

// ---------------------------------------------------------------------------
// Kernel Tt: g_tt[n][k] = Theta0[k][n] (k<256) | -Theta1[k-256][n] (k>=256)
// ---------------------------------------------------------------------------
__global__ void k_tt(const float* __restrict__ Theta) {
    __shared__ float t[32][33];
    const int kt = blockIdx.x * 32, nt = blockIdx.y * 32;
    const int tx = threadIdx.x & 31, ty = threadIdx.x >> 5;  // ty 0..7
#pragma unroll
    for (int r = 0; r < 32; r += 8) {
        int k = kt + ty + r;
        int n = nt + tx;
        float v = (k < 256) ? Theta[k * 256 + n] : -Theta[65536 + (k - 256) * 256 + n];
        t[ty + r][tx] = v;
    }
    __syncthreads();
#pragma unroll
    for (int r = 0; r < 32; r += 8) {
        int n = nt + ty + r;
        int k = kt + tx;
        g_tt[n * 512 + k] = t[tx][ty + r];
    }
}

// ---------------------------------------------------------------------------
// Kernel C: y[b,j,l] = rcs[b,j] * sum_i tmpS[b,i,j] * x[b,i,l]
// grid (4 l, 4 j, 32 b) = 512 CTAs, 128 threads, 32j x 64l tile, 4x4/thread.
// ---------------------------------------------------------------------------
__global__ void k_y(const float* __restrict__ x) {
    __shared__ float sS[16][32];
    __shared__ float sX[16][64];
    const int b  = blockIdx.z;
    const int j0 = blockIdx.y * 32;
    const int l0 = blockIdx.x * 64;
    const int tid = threadIdx.x;
    const int tx = tid & 15, ty = tid >> 4;  // ty 0..7

    float acc[4][4];
#pragma unroll
    for (int r = 0; r < 4; r++)
#pragma unroll
        for (int c = 0; c < 4; c++) acc[r][c] = 0.f;

    const float* Sb = g_tmpS + b * CC_;
    const float* Xb = x + b * C_ * L_;

#pragma unroll 1
    for (int i0 = 0; i0 < C_; i0 += 16) {
        __syncthreads();
#pragma unroll
        for (int rep = 0; rep < 4; rep++) {
            int idx = rep * 128 + tid;
            int r = idx >> 5, c = idx & 31;
            sS[r][c] = Sb[(i0 + r) * C_ + j0 + c];
        }
#pragma unroll
        for (int rep = 0; rep < 8; rep++) {
            int idx = rep * 128 + tid;
            int r = idx >> 6, c = idx & 63;
            sX[r][c] = Xb[(i0 + r) * L_ + l0 + c];
        }
        __syncthreads();
#pragma unroll
        for (int i = 0; i < 16; i++) {
            float4 av = *reinterpret_cast<const float4*>(&sS[i][ty * 4]);
            float4 bv = *reinterpret_cast<const float4*>(&sX[i][tx * 4]);
            float a4[4] = {av.x, av.y, av.z, av.w};
            float b4[4] = {bv.x, bv.y, bv.z, bv.w};
#pragma unroll
            for (int r = 0; r < 4; r++)
#pragma unroll
                for (int c = 0; c < 4; c++)
                    acc[r][c] += a4[r] * b4[c];
        }
    }
#pragma unroll
    for (int r = 0; r < 4; r++) {
        int jj = j0 + ty * 4 + r;
        float rc = g_rcs[b * C_ + jj];
        float4 v = make_float4(acc[r][0] * rc, acc[r][1] * rc,
                               acc[r][2] * rc, acc[r][3] * rc);
        *reinterpret_cast<float4*>(&g_y[b * C_ * L_ + jj * L_ + l0 + tx * 4]) = v;
    }
}

// ---------------------------------------------------------------------------
// Kernel D (tensor core, mma.sync tf32, 3-pass hi/lo split):
//   out = relu( [x | g_y] @ g_tt^T ),  M=4096, N=256, K=512
// CTA: 64x64 tile, 128 threads (4 warps in 2x2, 32x32 warp tiles).
// grid (4 n, 64 m) = 256 CTAs. K-chunks of 32, smem padded to 36 floats/row.
// ---------------------------------------------------------------------------
__global__ void __launch_bounds__(128) k_out_mma(const float* __restrict__ x,
                                                 float* __restrict__ out) {
    __shared__ float sAH[64][36], sAL[64][36];
    __shared__ float sBH[64][36], sBL[64][36];

    const int tid  = threadIdx.x;
    const int lane = tid & 31, wid = tid >> 5;
    const int n0 = blockIdx.x * 64;
    const int r0 = blockIdx.y * 64;
    const int wm = (wid >> 1) * 32;
    const int wn = (wid & 1) * 32;
    const int qr = lane >> 2;
    const int qc = lane & 3;

    float acc[2][4][4];
#pragma unroll
    for (int mi = 0; mi < 2; mi++)
#pragma unroll
        for (int ni = 0; ni < 4; ni++)
#pragma unroll
            for (int e = 0; e < 4; e++) acc[mi][ni][e] = 0.f;

#pragma unroll 1
    for (int s = 0; s < 16; s++) {
        const float* Asrc = (s < 8) ? (x   + (size_t)r0 * L_ + s * 32)
                                    : (g_y + (size_t)r0 * L_ + (s - 8) * 32);
        const float* Bsrc = g_tt + (size_t)n0 * 512 + s * 32;

        __syncthreads();
#pragma unroll
        for (int it = 0; it < 4; it++) {
            int idx = it * 128 + tid;
            int row = idx >> 3, c4 = (idx & 7) * 4;
            float4 v = *reinterpret_cast<const float4*>(Asrc + row * L_ + c4);
            float4 h = make_float4(tf32_hi(v.x), tf32_hi(v.y), tf32_hi(v.z), tf32_hi(v.w));
            float4 l = make_float4(cvt_tf32(v.x - h.x), cvt_tf32(v.y - h.y),
                                   cvt_tf32(v.z - h.z), cvt_tf32(v.w - h.w));
            *reinterpret_cast<float4*>(&sAH[row][c4]) = h;
            *reinterpret_cast<float4*>(&sAL[row][c4]) = l;

            float4 w = *reinterpret_cast<const float4*>(Bsrc + row * 512 + c4);
            float4 hb = make_float4(tf32_hi(w.x), tf32_hi(w.y), tf32_hi(w.z), tf32_hi(w.w));
            float4 lb = make_float4(cvt_tf32(w.x - hb.x), cvt_tf32(w.y - hb.y),
                                    cvt_tf32(w.z - hb.z), cvt_tf32(w.w - hb.w));
            *reinterpret_cast<float4*>(&sBH[row][c4]) = hb;
            *reinterpret_cast<float4*>(&sBL[row][c4]) = lb;
        }
        __syncthreads();

#pragma unroll
        for (int k8 = 0; k8 < 4; k8++) {
            const int k = k8 * 8;
            uint32_t ah[2][4], al[2][4], bh[4][2], bl[4][2];
#pragma unroll
            for (int mi = 0; mi < 2; mi++) {
                int r = wm + mi * 16 + qr;
                ah[mi][0] = __float_as_uint(sAH[r    ][k + qc    ]);
                ah[mi][1] = __float_as_uint(sAH[r + 8][k + qc    ]);
                ah[mi][2] = __float_as_uint(sAH[r    ][k + qc + 4]);
                ah[mi][3] = __float_as_uint(sAH[r + 8][k + qc + 4]);
                al[mi][0] = __float_as_uint(sAL[r    ][k + qc    ]);
                al[mi][1] = __float_as_uint(sAL[r + 8][k + qc    ]);
                al[mi][2] = __float_as_uint(sAL[r    ][k + qc + 4]);
                al[mi][3] = __float_as_uint(sAL[r + 8][k + qc + 4]);
            }
#pragma unroll
            for (int ni = 0; ni < 4; ni++) {
                int n = wn + ni * 8 + qr;
                bh[ni][0] = __float_as_uint(sBH[n][k + qc    ]);
                bh[ni][1] = __float_as_uint(sBH[n][k + qc + 4]);
                bl[ni][0] = __float_as_uint(sBL[n][k + qc    ]);
                bl[ni][1] = __float_as_uint(sBL[n][k + qc + 4]);
            }
#pragma unroll
            for (int mi = 0; mi < 2; mi++)
#pragma unroll
                for (int ni = 0; ni < 4; ni++)
                    mma_16n8k8(acc[mi][ni], ah[mi], bh[ni]);
#pragma unroll
            for (int mi = 0; mi < 2; mi++)
#pragma unroll
                for (int ni = 0; ni < 4; ni++)
                    mma_16n8k8(acc[mi][ni], al[mi], bh[ni]);
#pragma unroll
            for (int mi = 0; mi < 2; mi++)
#pragma unroll
                for (int ni = 0; ni < 4; ni++)
                    mma_16n8k8(acc[mi][ni], ah[mi], bl[ni]);
        }
    }

#pragma unroll
    for (int mi = 0; mi < 2; mi++) {
        int row = r0 + wm + mi * 16 + qr;
#pragma unroll
        for (int ni = 0; ni < 4; ni++) {
            int col = n0 + wn + ni * 8 + qc * 2;
            float2 v0 = make_float2(fmaxf(acc[mi][ni][0], 0.f),
                                    fmaxf(acc[mi][ni][1], 0.f));
            float2 v1 = make_float2(fmaxf(acc[mi][ni][2], 0.f),
                                    fmaxf(acc[mi][ni][3], 0.f));
            *reinterpret_cast<float2*>(out + (size_t)row * L_ + col) = v0;
            *reinterpret_cast<float2*>(out + (size_t)(row + 8) * L_ + col) = v1;
        }
    }
}

// ---------------------------------------------------------------------------
extern "C" void kernel_launch(void* const* d_in, const int* in_sizes, int n_in,
                              void* d_out, int out_size) {
    const float* x     = (const float*)d_in[0];   // [32,128,256]
    const float* a     = (const float*)d_in[1];   // [128,128]
    const float* Theta = (const float*)d_in[2];   // [2,256,256]
    float* out = (float*)d_out;                   // [32,128,256]

    k_tt    <<<dim3(16, 8),    256>>>(Theta);
    k_diff  <<<dim3(8, 32),    256>>>(x);
    k_rnorm <<<64,             256>>>();
    k_tmps  <<<dim3(32, 4),    256>>>(a);
    k_y     <<<dim3(4, 4, 32), 128>>>(x);
    k_out_mma<<<dim3(4, 64),   128>>>(x, out);
}

// round 5
// speedup vs baseline: 1.5969x; 1.0685x over previous
#include <cuda_runtime.h>
#include <cstdint>

#define B_  32
#define C_  128
#define L_  256
#define CC_ (C_ * C_)      // 16384
#define BCC_ (B_ * CC_)    // 524288

// Scratch (device globals — no allocations allowed)
__device__ float g_diff[BCC_];        // [b][i][j] pairwise L1
__device__ float g_tmpS[BCC_];        // exp(relu((1-diffn)*a))
__device__ float g_rcs[B_ * C_];      // 1 / column sums of tmpS
__device__ float g_y[B_ * C_ * L_];   // adj^T x  (rcs folded in)
__device__ float g_tt[256 * 512];     // B operand: [n][k] K-major, sign-folded

// ===========================================================================
// helpers
// ===========================================================================
__device__ __forceinline__ float tf32_hi(float v) {
    return __uint_as_float(__float_as_uint(v) & 0xFFFFE000u);
}
__device__ __forceinline__ float cvt_tf32(float v) {
    uint32_t r;
    asm("cvt.rna.tf32.f32 %0, %1;" : "=r"(r) : "f"(v));
    return __uint_as_float(r);
}
__device__ __forceinline__ void mma_16n8k8(float c[4], const uint32_t a[4],
                                           const uint32_t b[2]) {
    asm volatile(
        "mma.sync.aligned.m16n8k8.row.col.f32.tf32.tf32.f32 "
        "{%0,%1,%2,%3}, {%4,%5,%6,%7}, {%8,%9}, {%0,%1,%2,%3};"
        : "+f"(c[0]), "+f"(c[1]), "+f"(c[2]), "+f"(c[3])
        : "r"(a[0]), "r"(a[1]), "r"(a[2]), "r"(a[3]), "r"(b[0]), "r"(b[1]));
}

// ---------------------------------------------------------------------------
// Kernel A (symmetric): diff[b,i,j] = sum_l |x[b,i,l] - x[b,j,l]|
// Tile-pair decomposition: 36 pairs (ti<=tj) of 16x16 tiles x 32 b = 1152 CTAs,
// 256 threads, one (i,j) per thread, 4 accumulator chains over L=256.
// Mirror-writes the transposed tile when ti != tj.
// ---------------------------------------------------------------------------
__global__ void __launch_bounds__(256) k_diff(const float* __restrict__ x) {
    __shared__ float sxi[16][260];
    __shared__ float sxj[16][260];

    const int b = blockIdx.y;
    // pair index -> (ti, tj), ti <= tj, over 8 tiles
    int rem = blockIdx.x, ti = 0;
    while (rem >= 8 - ti) { rem -= 8 - ti; ti++; }
    const int tj = ti + rem;
    const int i0 = ti * 16, j0 = tj * 16;

    const int tid = threadIdx.x;
    const float* xb = x + b * C_ * L_;

    // load 16 rows of x for the i-tile and j-tile (float4, coalesced)
#pragma unroll
    for (int rep = 0; rep < 4; rep++) {
        int idx = rep * 256 + tid;         // 0..1023 float4 slots
        int row = idx >> 6, c4 = (idx & 63) * 4;
        *reinterpret_cast<float4*>(&sxi[row][c4]) =
            *reinterpret_cast<const float4*>(xb + (i0 + row) * L_ + c4);
        *reinterpret_cast<float4*>(&sxj[row][c4]) =
            *reinterpret_cast<const float4*>(xb + (j0 + row) * L_ + c4);
    }
    __syncthreads();

    const int ii = tid >> 4, jj = tid & 15;
    const float* ri = &sxi[ii][0];
    const float* rj = &sxj[jj][0];

    float a0 = 0.f, a1 = 0.f, a2 = 0.f, a3 = 0.f;
#pragma unroll
    for (int l = 0; l < L_; l += 16) {
        float4 u0 = *reinterpret_cast<const float4*>(ri + l);
        float4 v0 = *reinterpret_cast<const float4*>(rj + l);
        float4 u1 = *reinterpret_cast<const float4*>(ri + l + 4);
        float4 v1 = *reinterpret_cast<const float4*>(rj + l + 4);
        float4 u2 = *reinterpret_cast<const float4*>(ri + l + 8);
        float4 v2 = *reinterpret_cast<const float4*>(rj + l + 8);
        float4 u3 = *reinterpret_cast<const float4*>(ri + l + 12);
        float4 v3 = *reinterpret_cast<const float4*>(rj + l + 12);
        a0 += fabsf(u0.x - v0.x) + fabsf(u0.y - v0.y)
            + fabsf(u0.z - v0.z) + fabsf(u0.w - v0.w);
        a1 += fabsf(u1.x - v1.x) + fabsf(u1.y - v1.y)
            + fabsf(u1.z - v1.z) + fabsf(u1.w - v1.w);
        a2 += fabsf(u2.x - v2.x) + fabsf(u2.y - v2.y)
            + fabsf(u2.z - v2.z) + fabsf(u2.w - v2.w);
        a3 += fabsf(u3.x - v3.x) + fabsf(u3.y - v3.y)
            + fabsf(u3.z - v3.z) + fabsf(u3.w - v3.w);
    }
    float res = (a0 + a1) + (a2 + a3);

    g_diff[b * CC_ + (i0 + ii) * C_ + (j0 + jj)] = res;
    if (ti != tj)
        g_diff[b * CC_ + (j0 + jj) * C_ + (i0 + ii)] = res;
}

// ---------------------------------------------------------------------------
// Kernel B (fused norm+tmps, fully elementwise): thread per (i,j) pair.
// Holds diff[b] for all 32 b in registers: one g_diff pass, local rnorm,
// 32 independent exps. grid 128 x 128 threads.
// ---------------------------------------------------------------------------
__global__ void __launch_bounds__(128) k_nt(const float* __restrict__ a) {
    const int ij = blockIdx.x * 128 + threadIdx.x;

    float d[B_];
#pragma unroll
    for (int b = 0; b < B_; b++) d[b] = g_diff[b * CC_ + ij];

    float ss = 0.f;
#pragma unroll
    for (int b = 0; b < B_; b++) ss += d[b] * d[b];
    const float rn  = 1.f / fmaxf(sqrtf(ss), 1e-12f);
    const float aij = a[ij];

#pragma unroll
    for (int b = 0; b < B_; b++) {
        float v = __expf(fmaxf((1.f - d[b] * rn) * aij, 0.f));
        g_tmpS[b * CC_ + ij] = v;
    }
}

// ---------------------------------------------------------------------------
// Kernel B2: rcs[b,j] = 1 / sum_i tmpS[b,i,j]
// grid (32 b, 4 j-tiles) x 128 threads (ty=i-group 0..3, tx=j-lane 0..31).
// ---------------------------------------------------------------------------
__global__ void k_rcs() {
    __shared__ float red[4][32];
    const int b  = blockIdx.x;
    const int j  = blockIdx.y * 32 + (threadIdx.x & 31);
    const int ty = threadIdx.x >> 5;   // 0..3

    float cs = 0.f;
#pragma unroll
    for (int ii = 0; ii < 32; ii++) {
        int i = ii * 4 + ty;
        cs += g_tmpS[b * CC_ + i * C_ + j];
    }
    red[ty][threadIdx.x & 31] = cs;
    __syncthreads();
    if (ty == 0) {
        float s = red[0][threadIdx.x] + red[1][threadIdx.x]
                + red[2][threadIdx.x] + red[3][threadIdx.x];
        g_rcs[b * C_ + j] = 1.f / s;
    }
}

// ---------------------------------------------------------------------------
// Kernel Tt: g_tt[n][k] = Theta0[k][n] (k<256) | -Theta1[k-256][n] (k>=256)
// ---------------------------------------------------------------------------
__global__ void k_tt(const float* __restrict__ Theta) {
    __shared__ float t[32][33];
    const int kt = blockIdx.x * 32, nt = blockIdx.y * 32;
    const int tx = threadIdx.x & 31, ty = threadIdx.x >> 5;  // ty 0..7
#pragma unroll
    for (int r = 0; r < 32; r += 8) {
        int k = kt + ty + r;
        int n = nt + tx;
        float v = (k < 256) ? Theta[k * 256 + n] : -Theta[65536 + (k - 256) * 256 + n];
        t[ty + r][tx] = v;
    }
    __syncthreads();
#pragma unroll
    for (int r = 0; r < 32; r += 8) {
        int n = nt + ty + r;
        int k = kt + tx;
        g_tt[n * 512 + k] = t[tx][ty + r];
    }
}

// ---------------------------------------------------------------------------
// Kernel C: y[b,j,l] = rcs[b,j] * sum_i tmpS[b,i,j] * x[b,i,l]
// grid (4 l, 4 j, 32 b) = 512 CTAs, 128 threads, 32j x 64l tile, 4x4/thread.
// ---------------------------------------------------------------------------
__global__ void k_y(const float* __restrict__ x) {
    __shared__ float sS[16][32];
    __shared__ float sX[16][64];
    const int b  = blockIdx.z;
    const int j0 = blockIdx.y * 32;
    const int l0 = blockIdx.x * 64;
    const int tid = threadIdx.x;
    const int tx = tid & 15, ty = tid >> 4;  // ty 0..7

    float acc[4][4];
#pragma unroll
    for (int r = 0; r < 4; r++)
#pragma unroll
        for (int c = 0; c < 4; c++) acc[r][c] = 0.f;

    const float* Sb = g_tmpS + b * CC_;
    const float* Xb = x + b * C_ * L_;

#pragma unroll 1
    for (int i0 = 0; i0 < C_; i0 += 16) {
        __syncthreads();
#pragma unroll
        for (int rep = 0; rep < 4; rep++) {
            int idx = rep * 128 + tid;
            int r = idx >> 5, c = idx & 31;
            sS[r][c] = Sb[(i0 + r) * C_ + j0 + c];
        }
#pragma unroll
        for (int rep = 0; rep < 8; rep++) {
            int idx = rep * 128 + tid;
            int r = idx >> 6, c = idx & 63;
            sX[r][c] = Xb[(i0 + r) * L_ + l0 + c];
        }
        __syncthreads();
#pragma unroll
        for (int i = 0; i < 16; i++) {
            float4 av = *reinterpret_cast<const float4*>(&sS[i][ty * 4]);
            float4 bv = *reinterpret_cast<const float4*>(&sX[i][tx * 4]);
            float a4[4] = {av.x, av.y, av.z, av.w};
            float b4[4] = {bv.x, bv.y, bv.z, bv.w};
#pragma unroll
            for (int r = 0; r < 4; r++)
#pragma unroll
                for (int c = 0; c < 4; c++)
                    acc[r][c] += a4[r] * b4[c];
        }
    }
#pragma unroll
    for (int r = 0; r < 4; r++) {
        int jj = j0 + ty * 4 + r;
        float rc = g_rcs[b * C_ + jj];
        float4 v = make_float4(acc[r][0] * rc, acc[r][1] * rc,
                               acc[r][2] * rc, acc[r][3] * rc);
        *reinterpret_cast<float4*>(&g_y[b * C_ * L_ + jj * L_ + l0 + tx * 4]) = v;
    }
}

// ---------------------------------------------------------------------------
// Kernel D (tensor core, mma.sync tf32, 3-pass hi/lo split):
//   out = relu( [x | g_y] @ g_tt^T ),  M=4096, N=256, K=512
// ---------------------------------------------------------------------------
__global__ void __launch_bounds__(128) k_out_mma(const float* __restrict__ x,
                                                 float* __restrict__ out) {
    __shared__ float sAH[64][36], sAL[64][36];
    __shared__ float sBH[64][36], sBL[64][36];

    const int tid  = threadIdx.x;
    const int lane = tid & 31, wid = tid >> 5;
    const int n0 = blockIdx.x * 64;
    const int r0 = blockIdx.y * 64;
    const int wm = (wid >> 1) * 32;
    const int wn = (wid & 1) * 32;
    const int qr = lane >> 2;
    const int qc = lane & 3;

    float acc[2][4][4];
#pragma unroll
    for (int mi = 0; mi < 2; mi++)
#pragma unroll
        for (int ni = 0; ni < 4; ni++)
#pragma unroll
            for (int e = 0; e < 4; e++) acc[mi][ni][e] = 0.f;

#pragma unroll 1
    for (int s = 0; s < 16; s++) {
        const float* Asrc = (s < 8) ? (x   + (size_t)r0 * L_ + s * 32)
                                    : (g_y + (size_t)r0 * L_ + (s - 8) * 32);
        const float* Bsrc = g_tt + (size_t)n0 * 512 + s * 32;

        __syncthreads();
#pragma unroll
        for (int it = 0; it < 4; it++) {
            int idx = it * 128 + tid;
            int row = idx >> 3, c4 = (idx & 7) * 4;
            float4 v = *reinterpret_cast<const float4*>(Asrc + row * L_ + c4);
            float4 h = make_float4(tf32_hi(v.x), tf32_hi(v.y), tf32_hi(v.z), tf32_hi(v.w));
            float4 l = make_float4(cvt_tf32(v.x - h.x), cvt_tf32(v.y - h.y),
                                   cvt_tf32(v.z - h.z), cvt_tf32(v.w - h.w));
            *reinterpret_cast<float4*>(&sAH[row][c4]) = h;
            *reinterpret_cast<float4*>(&sAL[row][c4]) = l;

            float4 w = *reinterpret_cast<const float4*>(Bsrc + row * 512 + c4);
            float4 hb = make_float4(tf32_hi(w.x), tf32_hi(w.y), tf32_hi(w.z), tf32_hi(w.w));
            float4 lb = make_float4(cvt_tf32(w.x - hb.x), cvt_tf32(w.y - hb.y),
                                    cvt_tf32(w.z - hb.z), cvt_tf32(w.w - hb.w));
            *reinterpret_cast<float4*>(&sBH[row][c4]) = hb;
            *reinterpret_cast<float4*>(&sBL[row][c4]) = lb;
        }
        __syncthreads();

#pragma unroll
        for (int k8 = 0; k8 < 4; k8++) {
            const int k = k8 * 8;
            uint32_t ah[2][4], al[2][4], bh[4][2], bl[4][2];
#pragma unroll
            for (int mi = 0; mi < 2; mi++) {
                int r = wm + mi * 16 + qr;
                ah[mi][0] = __float_as_uint(sAH[r    ][k + qc    ]);
                ah[mi][1] = __float_as_uint(sAH[r + 8][k + qc    ]);
                ah[mi][2] = __float_as_uint(sAH[r    ][k + qc + 4]);
                ah[mi][3] = __float_as_uint(sAH[r + 8][k + qc + 4]);
                al[mi][0] = __float_as_uint(sAL[r    ][k + qc    ]);
                al[mi][1] = __float_as_uint(sAL[r + 8][k + qc    ]);
                al[mi][2] = __float_as_uint(sAL[r    ][k + qc + 4]);
                al[mi][3] = __float_as_uint(sAL[r + 8][k + qc + 4]);
            }
#pragma unroll
            for (int ni = 0; ni < 4; ni++) {
                int n = wn + ni * 8 + qr;
                bh[ni][0] = __float_as_uint(sBH[n][k + qc    ]);
                bh[ni][1] = __float_as_uint(sBH[n][k + qc + 4]);
                bl[ni][0] = __float_as_uint(sBL[n][k + qc    ]);
                bl[ni][1] = __float_as_uint(sBL[n][k + qc + 4]);
            }
#pragma unroll
            for (int mi = 0; mi < 2; mi++)
#pragma unroll
                for (int ni = 0; ni < 4; ni++)
                    mma_16n8k8(acc[mi][ni], ah[mi], bh[ni]);
#pragma unroll
            for (int mi = 0; mi < 2; mi++)
#pragma unroll
                for (int ni = 0; ni < 4; ni++)
                    mma_16n8k8(acc[mi][ni], al[mi], bh[ni]);
#pragma unroll
            for (int mi = 0; mi < 2; mi++)
#pragma unroll
                for (int ni = 0; ni < 4; ni++)
                    mma_16n8k8(acc[mi][ni], ah[mi], bl[ni]);
        }
    }

#pragma unroll
    for (int mi = 0; mi < 2; mi++) {
        int row = r0 + wm + mi * 16 + qr;
#pragma unroll
        for (int ni = 0; ni < 4; ni++) {
            int col = n0 + wn + ni * 8 + qc * 2;
            float2 v0 = make_float2(fmaxf(acc[mi][ni][0], 0.f),
                                    fmaxf(acc[mi][ni][1], 0.f));
            float2 v1 = make_float2(fmaxf(acc[mi][ni][2], 0.f),
                                    fmaxf(acc[mi][ni][3], 0.f));
            *reinterpret_cast<float2*>(out + (size_t)row * L_ + col) = v0;
            *reinterpret_cast<float2*>(out + (size_t)(row + 8) * L_ + col) = v1;
        }
    }
}

// ---------------------------------------------------------------------------
extern "C" void kernel_launch(void* const* d_in, const int* in_sizes, int n_in,
                              void* d_out, int out_size) {
    const float* x     = (const float*)d_in[0];   // [32,128,256]
    const float* a     = (const float*)d_in[1];   // [128,128]
    const float* Theta = (const float*)d_in[2];   // [2,256,256]
    float* out = (float*)d_out;                   // [32,128,256]

    k_tt    <<<dim3(16, 8),    256>>>(Theta);
    k_diff  <<<dim3(36, 32),   256>>>(x);
    k_nt    <<<128,            128>>>(a);
    k_rcs   <<<dim3(32, 4),    128>>>();
    k_y     <<<dim3(4, 4, 32), 128>>>(x);
    k_out_mma<<<dim3(4, 64),   128>>>(x, out);
}

// round 6
// speedup vs baseline: 1.7499x; 1.0958x over previous
#include <cuda_runtime.h>
#include <cstdint>

#define B_  32
#define C_  128
#define L_  256
#define CC_ (C_ * C_)      // 16384
#define BCC_ (B_ * CC_)    // 524288

// Scratch (device globals — no allocations allowed)
__device__ float g_diff[BCC_];        // [b][i][j] pairwise L1
__device__ float g_tmpS[BCC_];        // exp(relu((1-diffn)*a))
__device__ float g_y[B_ * C_ * L_];   // adj^T x  (column-normalized)
__device__ float g_tt[256 * 512];     // B operand: [n][k] K-major, sign-folded

// ===========================================================================
// helpers
// ===========================================================================
__device__ __forceinline__ float tf32_hi(float v) {
    return __uint_as_float(__float_as_uint(v) & 0xFFFFE000u);
}
__device__ __forceinline__ float cvt_tf32(float v) {
    uint32_t r;
    asm("cvt.rna.tf32.f32 %0, %1;" : "=r"(r) : "f"(v));
    return __uint_as_float(r);
}
__device__ __forceinline__ void mma_16n8k8(float c[4], const uint32_t a[4],
                                           const uint32_t b[2]) {
    asm volatile(
        "mma.sync.aligned.m16n8k8.row.col.f32.tf32.tf32.f32 "
        "{%0,%1,%2,%3}, {%4,%5,%6,%7}, {%8,%9}, {%0,%1,%2,%3};"
        : "+f"(c[0]), "+f"(c[1]), "+f"(c[2]), "+f"(c[3])
        : "r"(a[0]), "r"(a[1]), "r"(a[2]), "r"(a[3]), "r"(b[0]), "r"(b[1]));
}

// ---------------------------------------------------------------------------
// Kernel A (merged): blockIdx.x < 36  -> symmetric pairwise-L1 diff tile
//                    blockIdx.x >= 36 -> Theta transpose/sign-fold into g_tt
// grid (40, 32), 256 threads.
// ---------------------------------------------------------------------------
__global__ void __launch_bounds__(256) k_ttdiff(const float* __restrict__ x,
                                                const float* __restrict__ Theta) {
    __shared__ float sxi[16][260];
    __shared__ float sxj[16][260];

    if (blockIdx.x >= 36) {
        // ---- Theta transpose part: 4 x 32 = 128 virtual blocks ----
        __shared__ float t[32][33];
        const int id = (blockIdx.x - 36) * 32 + blockIdx.y;   // 0..127
        const int kt = (id >> 3) * 32, nt = (id & 7) * 32;
        const int tx = threadIdx.x & 31, ty = threadIdx.x >> 5;  // ty 0..7
#pragma unroll
        for (int r = 0; r < 32; r += 8) {
            int k = kt + ty + r;
            int n = nt + tx;
            float v = (k < 256) ? Theta[k * 256 + n]
                                : -Theta[65536 + (k - 256) * 256 + n];
            t[ty + r][tx] = v;
        }
        __syncthreads();
#pragma unroll
        for (int r = 0; r < 32; r += 8) {
            int n = nt + ty + r;
            int k = kt + tx;
            g_tt[n * 512 + k] = t[tx][ty + r];
        }
        return;
    }

    // ---- diff part: tile-pair (ti<=tj) of 16x16, mirror-write ----
    const int b = blockIdx.y;
    int rem = blockIdx.x, ti = 0;
    while (rem >= 8 - ti) { rem -= 8 - ti; ti++; }
    const int tj = ti + rem;
    const int i0 = ti * 16, j0 = tj * 16;

    const int tid = threadIdx.x;
    const float* xb = x + b * C_ * L_;

#pragma unroll
    for (int rep = 0; rep < 4; rep++) {
        int idx = rep * 256 + tid;
        int row = idx >> 6, c4 = (idx & 63) * 4;
        *reinterpret_cast<float4*>(&sxi[row][c4]) =
            *reinterpret_cast<const float4*>(xb + (i0 + row) * L_ + c4);
        *reinterpret_cast<float4*>(&sxj[row][c4]) =
            *reinterpret_cast<const float4*>(xb + (j0 + row) * L_ + c4);
    }
    __syncthreads();

    const int ii = tid >> 4, jj = tid & 15;
    const float* ri = &sxi[ii][0];
    const float* rj = &sxj[jj][0];

    float a0 = 0.f, a1 = 0.f, a2 = 0.f, a3 = 0.f;
#pragma unroll
    for (int l = 0; l < L_; l += 16) {
        float4 u0 = *reinterpret_cast<const float4*>(ri + l);
        float4 v0 = *reinterpret_cast<const float4*>(rj + l);
        float4 u1 = *reinterpret_cast<const float4*>(ri + l + 4);
        float4 v1 = *reinterpret_cast<const float4*>(rj + l + 4);
        float4 u2 = *reinterpret_cast<const float4*>(ri + l + 8);
        float4 v2 = *reinterpret_cast<const float4*>(rj + l + 8);
        float4 u3 = *reinterpret_cast<const float4*>(ri + l + 12);
        float4 v3 = *reinterpret_cast<const float4*>(rj + l + 12);
        a0 += fabsf(u0.x - v0.x) + fabsf(u0.y - v0.y)
            + fabsf(u0.z - v0.z) + fabsf(u0.w - v0.w);
        a1 += fabsf(u1.x - v1.x) + fabsf(u1.y - v1.y)
            + fabsf(u1.z - v1.z) + fabsf(u1.w - v1.w);
        a2 += fabsf(u2.x - v2.x) + fabsf(u2.y - v2.y)
            + fabsf(u2.z - v2.z) + fabsf(u2.w - v2.w);
        a3 += fabsf(u3.x - v3.x) + fabsf(u3.y - v3.y)
            + fabsf(u3.z - v3.z) + fabsf(u3.w - v3.w);
    }
    float res = (a0 + a1) + (a2 + a3);

    g_diff[b * CC_ + (i0 + ii) * C_ + (j0 + jj)] = res;
    if (ti != tj)
        g_diff[b * CC_ + (j0 + jj) * C_ + (i0 + ii)] = res;
}

// ---------------------------------------------------------------------------
// Kernel B (fused norm+tmps, fully elementwise): thread per (i,j) pair.
// Holds diff[b] for all 32 b in registers: one g_diff pass, local rnorm,
// 32 independent exps. grid 128 x 128 threads.
// ---------------------------------------------------------------------------
__global__ void __launch_bounds__(128) k_nt(const float* __restrict__ a) {
    const int ij = blockIdx.x * 128 + threadIdx.x;

    float d[B_];
#pragma unroll
    for (int b = 0; b < B_; b++) d[b] = g_diff[b * CC_ + ij];

    float ss = 0.f;
#pragma unroll
    for (int b = 0; b < B_; b++) ss += d[b] * d[b];
    const float rn  = 1.f / fmaxf(sqrtf(ss), 1e-12f);
    const float aij = a[ij];

#pragma unroll
    for (int b = 0; b < B_; b++) {
        float v = __expf(fmaxf((1.f - d[b] * rn) * aij, 0.f));
        g_tmpS[b * CC_ + ij] = v;
    }
}

// ---------------------------------------------------------------------------
// Kernel C: y[b,j,l] = (1/cs[b,j]) * sum_i tmpS[b,i,j] * x[b,i,l]
// Column sums cs computed in-kernel (threads 0..31 accumulate the smem tile),
// no separate k_rcs pass. grid (4 l, 4 j, 32 b) = 512 CTAs, 128 threads.
// ---------------------------------------------------------------------------
__global__ void k_y(const float* __restrict__ x) {
    __shared__ float sS[16][32];
    __shared__ float sX[16][64];
    __shared__ float srcs[32];
    const int b  = blockIdx.z;
    const int j0 = blockIdx.y * 32;
    const int l0 = blockIdx.x * 64;
    const int tid = threadIdx.x;
    const int tx = tid & 15, ty = tid >> 4;  // ty 0..7

    float acc[4][4];
#pragma unroll
    for (int r = 0; r < 4; r++)
#pragma unroll
        for (int c = 0; c < 4; c++) acc[r][c] = 0.f;
    float csum = 0.f;

    const float* Sb = g_tmpS + b * CC_;
    const float* Xb = x + b * C_ * L_;

#pragma unroll 1
    for (int i0 = 0; i0 < C_; i0 += 16) {
        __syncthreads();
#pragma unroll
        for (int rep = 0; rep < 4; rep++) {
            int idx = rep * 128 + tid;
            int r = idx >> 5, c = idx & 31;
            sS[r][c] = Sb[(i0 + r) * C_ + j0 + c];
        }
#pragma unroll
        for (int rep = 0; rep < 8; rep++) {
            int idx = rep * 128 + tid;
            int r = idx >> 6, c = idx & 63;
            sX[r][c] = Xb[(i0 + r) * L_ + l0 + c];
        }
        __syncthreads();
        if (tid < 32) {
#pragma unroll
            for (int r = 0; r < 16; r++) csum += sS[r][tid];
        }
#pragma unroll
        for (int i = 0; i < 16; i++) {
            float4 av = *reinterpret_cast<const float4*>(&sS[i][ty * 4]);
            float4 bv = *reinterpret_cast<const float4*>(&sX[i][tx * 4]);
            float a4[4] = {av.x, av.y, av.z, av.w};
            float b4[4] = {bv.x, bv.y, bv.z, bv.w};
#pragma unroll
            for (int r = 0; r < 4; r++)
#pragma unroll
                for (int c = 0; c < 4; c++)
                    acc[r][c] += a4[r] * b4[c];
        }
    }
    if (tid < 32) srcs[tid] = 1.f / csum;
    __syncthreads();

#pragma unroll
    for (int r = 0; r < 4; r++) {
        int jj = j0 + ty * 4 + r;
        float rc = srcs[ty * 4 + r];
        float4 v = make_float4(acc[r][0] * rc, acc[r][1] * rc,
                               acc[r][2] * rc, acc[r][3] * rc);
        *reinterpret_cast<float4*>(&g_y[b * C_ * L_ + jj * L_ + l0 + tx * 4]) = v;
    }
}

// ---------------------------------------------------------------------------
// Kernel D (tensor core, mma.sync tf32, 3-pass hi/lo split, SW-pipelined):
//   out = relu( [x | g_y] @ g_tt^T ),  M=4096, N=256, K=512
// CTA: 64x64 tile, 128 threads (4 warps 2x2). grid (4 n, 64 m) = 256 CTAs.
// Next K-slab is register-prefetched right after the smem handoff so global
// latency overlaps the 96 MMAs of the current slab.
// ---------------------------------------------------------------------------
__global__ void __launch_bounds__(128) k_out_mma(const float* __restrict__ x,
                                                 float* __restrict__ out) {
    __shared__ float sAH[64][36], sAL[64][36];
    __shared__ float sBH[64][36], sBL[64][36];

    const int tid  = threadIdx.x;
    const int lane = tid & 31, wid = tid >> 5;
    const int n0 = blockIdx.x * 64;
    const int r0 = blockIdx.y * 64;
    const int wm = (wid >> 1) * 32;
    const int wn = (wid & 1) * 32;
    const int qr = lane >> 2;
    const int qc = lane & 3;
    const int prow = tid >> 3, pc4 = (tid & 7) * 4;   // per-thread load coords

    float acc[2][4][4];
#pragma unroll
    for (int mi = 0; mi < 2; mi++)
#pragma unroll
        for (int ni = 0; ni < 4; ni++)
#pragma unroll
            for (int e = 0; e < 4; e++) acc[mi][ni][e] = 0.f;

    // prefetch slab 0
    float4 pA[4], pB[4];
    {
        const float* Asrc = x + (size_t)r0 * L_;
        const float* Bsrc = g_tt + (size_t)n0 * 512;
#pragma unroll
        for (int it = 0; it < 4; it++) {
            pA[it] = *reinterpret_cast<const float4*>(Asrc + (prow + it * 16) * L_ + pc4);
            pB[it] = *reinterpret_cast<const float4*>(Bsrc + (prow + it * 16) * 512 + pc4);
        }
    }

#pragma unroll 1
    for (int s = 0; s < 16; s++) {
        __syncthreads();
        // hand current slab to smem (hi/lo split)
#pragma unroll
        for (int it = 0; it < 4; it++) {
            int row = prow + it * 16;
            float4 v = pA[it];
            float4 h = make_float4(tf32_hi(v.x), tf32_hi(v.y), tf32_hi(v.z), tf32_hi(v.w));
            float4 l = make_float4(cvt_tf32(v.x - h.x), cvt_tf32(v.y - h.y),
                                   cvt_tf32(v.z - h.z), cvt_tf32(v.w - h.w));
            *reinterpret_cast<float4*>(&sAH[row][pc4]) = h;
            *reinterpret_cast<float4*>(&sAL[row][pc4]) = l;

            float4 w = pB[it];
            float4 hb = make_float4(tf32_hi(w.x), tf32_hi(w.y), tf32_hi(w.z), tf32_hi(w.w));
            float4 lb = make_float4(cvt_tf32(w.x - hb.x), cvt_tf32(w.y - hb.y),
                                    cvt_tf32(w.z - hb.z), cvt_tf32(w.w - hb.w));
            *reinterpret_cast<float4*>(&sBH[row][pc4]) = hb;
            *reinterpret_cast<float4*>(&sBL[row][pc4]) = lb;
        }
        __syncthreads();

        // prefetch next slab (overlaps the MMA work below)
        if (s < 15) {
            const int sn = s + 1;
            const float* Asrc = (sn < 8) ? (x   + (size_t)r0 * L_ + sn * 32)
                                         : (g_y + (size_t)r0 * L_ + (sn - 8) * 32);
            const float* Bsrc = g_tt + (size_t)n0 * 512 + sn * 32;
#pragma unroll
            for (int it = 0; it < 4; it++) {
                pA[it] = *reinterpret_cast<const float4*>(Asrc + (prow + it * 16) * L_ + pc4);
                pB[it] = *reinterpret_cast<const float4*>(Bsrc + (prow + it * 16) * 512 + pc4);
            }
        }

#pragma unroll
        for (int k8 = 0; k8 < 4; k8++) {
            const int k = k8 * 8;
            uint32_t ah[2][4], al[2][4], bh[4][2], bl[4][2];
#pragma unroll
            for (int mi = 0; mi < 2; mi++) {
                int r = wm + mi * 16 + qr;
                ah[mi][0] = __float_as_uint(sAH[r    ][k + qc    ]);
                ah[mi][1] = __float_as_uint(sAH[r + 8][k + qc    ]);
                ah[mi][2] = __float_as_uint(sAH[r    ][k + qc + 4]);
                ah[mi][3] = __float_as_uint(sAH[r + 8][k + qc + 4]);
                al[mi][0] = __float_as_uint(sAL[r    ][k + qc    ]);
                al[mi][1] = __float_as_uint(sAL[r + 8][k + qc    ]);
                al[mi][2] = __float_as_uint(sAL[r    ][k + qc + 4]);
                al[mi][3] = __float_as_uint(sAL[r + 8][k + qc + 4]);
            }
#pragma unroll
            for (int ni = 0; ni < 4; ni++) {
                int n = wn + ni * 8 + qr;
                bh[ni][0] = __float_as_uint(sBH[n][k + qc    ]);
                bh[ni][1] = __float_as_uint(sBH[n][k + qc + 4]);
                bl[ni][0] = __float_as_uint(sBL[n][k + qc    ]);
                bl[ni][1] = __float_as_uint(sBL[n][k + qc + 4]);
            }
#pragma unroll
            for (int mi = 0; mi < 2; mi++)
#pragma unroll
                for (int ni = 0; ni < 4; ni++)
                    mma_16n8k8(acc[mi][ni], ah[mi], bh[ni]);
#pragma unroll
            for (int mi = 0; mi < 2; mi++)
#pragma unroll
                for (int ni = 0; ni < 4; ni++)
                    mma_16n8k8(acc[mi][ni], al[mi], bh[ni]);
#pragma unroll
            for (int mi = 0; mi < 2; mi++)
#pragma unroll
                for (int ni = 0; ni < 4; ni++)
                    mma_16n8k8(acc[mi][ni], ah[mi], bl[ni]);
        }
    }

#pragma unroll
    for (int mi = 0; mi < 2; mi++) {
        int row = r0 + wm + mi * 16 + qr;
#pragma unroll
        for (int ni = 0; ni < 4; ni++) {
            int col = n0 + wn + ni * 8 + qc * 2;
            float2 v0 = make_float2(fmaxf(acc[mi][ni][0], 0.f),
                                    fmaxf(acc[mi][ni][1], 0.f));
            float2 v1 = make_float2(fmaxf(acc[mi][ni][2], 0.f),
                                    fmaxf(acc[mi][ni][3], 0.f));
            *reinterpret_cast<float2*>(out + (size_t)row * L_ + col) = v0;
            *reinterpret_cast<float2*>(out + (size_t)(row + 8) * L_ + col) = v1;
        }
    }
}

// ---------------------------------------------------------------------------
extern "C" void kernel_launch(void* const* d_in, const int* in_sizes, int n_in,
                              void* d_out, int out_size) {
    const float* x     = (const float*)d_in[0];   // [32,128,256]
    const float* a     = (const float*)d_in[1];   // [128,128]
    const float* Theta = (const float*)d_in[2];   // [2,256,256]
    float* out = (float*)d_out;                   // [32,128,256]

    k_ttdiff <<<dim3(40, 32),   256>>>(x, Theta);
    k_nt     <<<128,            128>>>(a);
    k_y      <<<dim3(4, 4, 32), 128>>>(x);
    k_out_mma<<<dim3(4, 64),    128>>>(x, out);
}